// round 8
// baseline (speedup 1.0000x reference)
#include <cuda_runtime.h>

#define T_STEPS 1000
#define C_CH    3
#define H_DIM   64
#define W_DIM   64
#define HW      (H_DIM * W_DIM)       // 4096
#define HW4     (HW / 4)              // 1024
#define PIX     (C_CH * HW)           // 12288
#define PIX4    (PIX / 4)             // 3072
#define NSEG    40
#define SEGLEN  (T_STEPS / NSEG)      // 25
#define TILE_ROWS 16

typedef unsigned long long u64t;

__device__ float g_E[(size_t)T_STEPS * PIX];      // ~49 MB scratch
__device__ float g_Psum[NSEG * PIX];              // ~2 MB
__device__ float2 g_wpack[81];                    // staging for packed weights
__constant__ float2 c_w2[81];                     // (w,w) packed, constant port

#define FMA2(d, a, b, c) \
    asm("fma.rn.f32x2 %0, %1, %2, %3;" : "=l"(d) : "l"(a), "l"(b), "l"(c))
#define MUL2(d, a, b) \
    asm("mul.rn.f32x2 %0, %1, %2;" : "=l"(d) : "l"(a), "l"(b))
#define PACK2(d, lo, hi) \
    asm("mov.b64 %0, {%1, %2};" : "=l"(d) : "f"(lo), "f"(hi))

__global__ void pack_w_kernel(const float* __restrict__ w)
{
    int i = threadIdx.x;
    if (i < 81) g_wpack[i] = make_float2(w[i], w[i]);
}

// ---------------------------------------------------------------------------
// Kernel A: 256 threads, one (16-row tile, image j).
// Thread = 1 row x 4 cols x 3 output channels; accumulators are packed
// column-pairs (f32x2), weights are (w,w) packs on the constant port.
// ---------------------------------------------------------------------------
__global__ __launch_bounds__(256, 4) void conv_kernel(
    const float* __restrict__ src,       // images 0..T-1, (.., C, H, W)
    const float* __restrict__ temb,      // (T, 3)
    const int*   __restrict__ t_arr,     // (T,)
    const float* __restrict__ et_coeff)  // (T,)
{
    __shared__ float4 s_in4[3][18][18];  // [ci][row][quad]; quad q = cols 4q-4..4q-1

    const int j   = blockIdx.y;
    const int r0  = blockIdx.x * TILE_ROWS;
    const int tid = threadIdx.x;
    const int h   = tid >> 4;            // row 0..15
    const int k   = tid & 15;            // col-group 0..15 (cols 4k..4k+3)

    // Single-pass staging: interior quads get global data, pads/halo get zero.
    const float4* img4 = (const float4*)(src + (size_t)j * PIX);
    for (int l = tid; l < 3 * 18 * 18; l += 256) {
        int ci  = l / 324;
        int rem = l - ci * 324;
        int r   = rem / 18;
        int q   = rem - r * 18;
        int gh  = r0 + r - 1;
        float4 v = make_float4(0.f, 0.f, 0.f, 0.f);
        if (q >= 1 && q <= 16 && gh >= 0 && gh < H_DIM)
            v = img4[ci * HW4 + gh * 16 + (q - 1)];
        (&s_in4[0][0][0])[l] = v;
    }
    __syncthreads();

    const int   trev = __ldg(t_arr + j);
    const float ec   = __ldg(et_coeff + j);

    // acc2[c][p]: packed pair for output channel c, columns (2p, 2p+1)
    u64t acc2[3][2];
#pragma unroll
    for (int c = 0; c < 3; c++) {
        const float tb = __ldg(temb + trev * 3 + c);
        u64t tb2; PACK2(tb2, tb, tb);
        acc2[c][0] = tb2; acc2[c][1] = tb2;
    }

#pragma unroll 1
    for (int ci = 0; ci < 3; ci++) {
        // P[r][d] = packed (v[d], v[d+1]) over the 6-col window per row.
        // B = (v1,v2,v3,v4) from one LDS.128: P[.][1] and P[.][3] are free.
        u64t P[3][5];
#pragma unroll
        for (int r = 0; r < 3; r++) {
            const float  v0 = ((const float*)&s_in4[ci][h + r][k])[3];
            const float4 B  = s_in4[ci][h + r][k + 1];
            const float  v5 = ((const float*)&s_in4[ci][h + r][k + 2])[0];
            PACK2(P[r][0], v0, B.x);
            P[r][1] = ((const u64t*)&B)[0];        // (v1, v2)
            PACK2(P[r][2], B.y, B.z);
            P[r][3] = ((const u64t*)&B)[1];        // (v3, v4)
            PACK2(P[r][4], B.w, v5);
        }
#pragma unroll
        for (int dh = 0; dh < 3; dh++)
#pragma unroll
            for (int dw = 0; dw < 3; dw++) {
                const int tap = ci * 9 + dh * 3 + dw;
                const u64t w0 = *(const u64t*)&c_w2[tap];
                const u64t w1 = *(const u64t*)&c_w2[27 + tap];
                const u64t w2 = *(const u64t*)&c_w2[54 + tap];
                const u64t xlo = P[dh][dw];        // cols (dw,   dw+1)
                const u64t xhi = P[dh][dw + 2];    // cols (dw+2, dw+3)
                FMA2(acc2[0][0], w0, xlo, acc2[0][0]);
                FMA2(acc2[0][1], w0, xhi, acc2[0][1]);
                FMA2(acc2[1][0], w1, xlo, acc2[1][0]);
                FMA2(acc2[1][1], w1, xhi, acc2[1][1]);
                FMA2(acc2[2][0], w2, xlo, acc2[2][0]);
                FMA2(acc2[2][1], w2, xhi, acc2[2][1]);
            }
    }

    u64t ec2; PACK2(ec2, ec, ec);
    float4* Ej4 = (float4*)(g_E + (size_t)j * PIX);
    const int gq = (r0 + h) * 16 + k;     // float4 index within a channel plane
#pragma unroll
    for (int c = 0; c < 3; c++) {
        u64t m0, m1;
        MUL2(m0, acc2[c][0], ec2);
        MUL2(m1, acc2[c][1], ec2);
        const float2 lo = *(const float2*)&m0;
        const float2 hi = *(const float2*)&m1;
        Ej4[c * HW4 + gq] = make_float4(lo.x, lo.y, hi.x, hi.y);
    }
}

// ---------------------------------------------------------------------------
// Kernel B: per-segment partial sums of E (float4, E hot in L2).
// ---------------------------------------------------------------------------
__global__ __launch_bounds__(256) void psum_kernel()
{
    const int p4  = blockIdx.x * 256 + threadIdx.x;   // < PIX4
    const int seg = blockIdx.y;
    const float4* base = (const float4*)g_E + (size_t)seg * SEGLEN * PIX4 + p4;
    float4 s = make_float4(0.f, 0.f, 0.f, 0.f);
#pragma unroll 5
    for (int j = 0; j < SEGLEN; j++) {
        float4 e = base[(size_t)j * PIX4];
        s.x += e.x; s.y += e.y; s.z += e.z; s.w += e.w;
    }
    ((float4*)g_Psum)[seg * PIX4 + p4] = s;
}

// ---------------------------------------------------------------------------
// Kernel C: cross-segment offset + local scan + combine (float4).
// ---------------------------------------------------------------------------
__global__ __launch_bounds__(128) void scan_combine_kernel(
    float*       __restrict__ dst,          // (T+1, C, H, W)
    const float* __restrict__ xT,           // first image of original x
    const float* __restrict__ alpha_ratio,  // (T,)
    const float* __restrict__ epc)          // (T,)
{
    const int seg = blockIdx.y;
    const int p4  = blockIdx.x * 128 + threadIdx.x;   // < PIX4

    float4 acc = make_float4(0.f, 0.f, 0.f, 0.f);
    for (int s = 0; s < seg; s++) {
        float4 ps = ((const float4*)g_Psum)[s * PIX4 + p4];
        acc.x += ps.x; acc.y += ps.y; acc.z += ps.z; acc.w += ps.w;
    }

    const float4 xv = ((const float4*)xT)[p4];
    if (seg == 0)
        ((float4*)dst)[p4] = xv;             // image 0 stays xT

    const int t0 = seg * SEGLEN;
#pragma unroll 5
    for (int j = t0; j < t0 + SEGLEN; j++) {
        float4 e = ((const float4*)g_E)[(size_t)j * PIX4 + p4];
        acc.x += e.x; acc.y += e.y; acc.z += e.z; acc.w += e.w;
        const float ar = __ldg(alpha_ratio + j);
        const float ep = __ldg(epc + j);
        float4 o;
        o.x = fmaf(ar, xv.x, ep * acc.x);
        o.y = fmaf(ar, xv.y, ep * acc.y);
        o.z = fmaf(ar, xv.z, ep * acc.z);
        o.w = fmaf(ar, xv.w, ep * acc.w);
        ((float4*)dst)[(size_t)(j + 1) * PIX4 + p4] = o;
    }
}

extern "C" void kernel_launch(void* const* d_in, const int* in_sizes, int n_in,
                              void* d_out, int out_size)
{
    const float* x           = (const float*)d_in[0];  // (T+1, 3, 64, 64)
    const int*   t_arr       = (const int*)  d_in[1];  // (T,)
    const float* alpha_ratio = (const float*)d_in[2];  // (T,1,1,1)
    const float* et_coeff    = (const float*)d_in[3];  // (T,1,1,1)
    const float* epc         = (const float*)d_in[4];  // (T,1,1,1)
    const float* conv_w      = (const float*)d_in[5];  // (3,3,3,3)
    const float* temb        = (const float*)d_in[6];  // (T, 3)
    float*       out         = (float*)d_out;

    // Duplicate weights to (w,w) packs, then stage into the constant bank.
    pack_w_kernel<<<1, 96>>>(conv_w);
    void* wp = nullptr;
    cudaGetSymbolAddress(&wp, g_wpack);
    cudaMemcpyToSymbolAsync(c_w2, wp, 81 * sizeof(float2), 0,
                            cudaMemcpyDeviceToDevice);

    dim3 gA(H_DIM / TILE_ROWS, T_STEPS), bA(256);      // (4, 1000)
    dim3 gB(PIX4 / 256, NSEG),           bB(256);      // (12, 40)
    dim3 gC(PIX4 / 128, NSEG),           bC(128);      // (24, 40)

    for (int it = 0; it < 3; it++) {
        const float* src = (it == 0) ? x : out;  // conv reads images 0..T-1
        conv_kernel<<<gA, bA>>>(src, temb, t_arr, et_coeff);
        psum_kernel<<<gB, bB>>>();
        scan_combine_kernel<<<gC, bC>>>(out, x, alpha_ratio, epc);
    }
}

// round 9
// speedup vs baseline: 1.0811x; 1.0811x over previous
#include <cuda_runtime.h>

#define T_STEPS 1000
#define C_CH    3
#define H_DIM   64
#define W_DIM   64
#define HW      (H_DIM * W_DIM)       // 4096
#define HW4     (HW / 4)              // 1024
#define PIX     (C_CH * HW)           // 12288
#define PIX4    (PIX / 4)             // 3072
#define NSEG    50
#define SEGLEN  (T_STEPS / NSEG)      // 20
#define TILE_ROWS 16

__device__ float g_E[(size_t)T_STEPS * PIX];      // ~49 MB scratch
__device__ float g_Psum[NSEG * PIX];              // ~2.5 MB
__device__ float g_Ppre[NSEG * PIX];              // exclusive prefix of g_Psum
__constant__ float c_w[81];                       // conv weights (LDCU port)

// ---------------------------------------------------------------------------
// Kernel A (R7 shape, proven): 256 threads, one (16-row tile, image j).
// Thread = 1 row x 4 cols x 3 output channels (12 accumulators).
// Inputs via LDS.128; weights via the constant port; ec applied at the end.
// ---------------------------------------------------------------------------
__global__ __launch_bounds__(256, 4) void conv_kernel(
    const float* __restrict__ src,       // images 0..T-1, (.., C, H, W)
    const float* __restrict__ temb,      // (T, 3)
    const int*   __restrict__ t_arr,     // (T,)
    const float* __restrict__ et_coeff)  // (T,)
{
    __shared__ float4 s_in4[3][18][18];  // [ci][row][quad]; quad q = cols 4q-4..4q-1

    const int j   = blockIdx.y;
    const int r0  = blockIdx.x * TILE_ROWS;
    const int tid = threadIdx.x;
    const int h   = tid >> 4;            // row 0..15
    const int k   = tid & 15;            // col-group 0..15 (cols 4k..4k+3)

    const float4* img4 = (const float4*)(src + (size_t)j * PIX);
    for (int l = tid; l < 3 * 18 * 18; l += 256) {
        int ci  = l / 324;
        int rem = l - ci * 324;
        int r   = rem / 18;
        int q   = rem - r * 18;
        int gh  = r0 + r - 1;
        float4 v = make_float4(0.f, 0.f, 0.f, 0.f);
        if (q >= 1 && q <= 16 && gh >= 0 && gh < H_DIM)
            v = img4[ci * HW4 + gh * 16 + (q - 1)];
        (&s_in4[0][0][0])[l] = v;
    }
    __syncthreads();

    const int   trev = __ldg(t_arr + j);
    const float ec   = __ldg(et_coeff + j);

    float acc[3][4];
#pragma unroll
    for (int c = 0; c < 3; c++) {
        const float tb = __ldg(temb + trev * 3 + c);
#pragma unroll
        for (int s = 0; s < 4; s++) acc[c][s] = tb;
    }

#pragma unroll 1
    for (int ci = 0; ci < 3; ci++) {
        float v[3][6];
#pragma unroll
        for (int r = 0; r < 3; r++) {
            float4 A = s_in4[ci][h + r][k];
            float4 B = s_in4[ci][h + r][k + 1];
            float4 C = s_in4[ci][h + r][k + 2];
            v[r][0] = A.w; v[r][1] = B.x; v[r][2] = B.y;
            v[r][3] = B.z; v[r][4] = B.w; v[r][5] = C.x;
        }
#pragma unroll
        for (int dh = 0; dh < 3; dh++)
#pragma unroll
            for (int dw = 0; dw < 3; dw++) {
                const int tap = ci * 9 + dh * 3 + dw;
                const float w0 = c_w[tap];
                const float w1 = c_w[27 + tap];
                const float w2 = c_w[54 + tap];
#pragma unroll
                for (int s = 0; s < 4; s++) {
                    const float xv = v[dh][dw + s];
                    acc[0][s] = fmaf(w0, xv, acc[0][s]);
                    acc[1][s] = fmaf(w1, xv, acc[1][s]);
                    acc[2][s] = fmaf(w2, xv, acc[2][s]);
                }
            }
    }

    float4* Ej4 = (float4*)(g_E + (size_t)j * PIX);
    const int gq = (r0 + h) * 16 + k;
#pragma unroll
    for (int c = 0; c < 3; c++)
        Ej4[c * HW4 + gq] = make_float4(acc[c][0] * ec, acc[c][1] * ec,
                                        acc[c][2] * ec, acc[c][3] * ec);
}

// ---------------------------------------------------------------------------
// Kernel B: per-segment partial sums of E (float4, E hot in L2).
// ---------------------------------------------------------------------------
__global__ __launch_bounds__(256) void psum_kernel()
{
    const int p4  = blockIdx.x * 256 + threadIdx.x;   // < PIX4
    const int seg = blockIdx.y;
    const float4* base = (const float4*)g_E + (size_t)seg * SEGLEN * PIX4 + p4;
    float4 s = make_float4(0.f, 0.f, 0.f, 0.f);
#pragma unroll 10
    for (int j = 0; j < SEGLEN; j++) {
        float4 e = base[(size_t)j * PIX4];
        s.x += e.x; s.y += e.y; s.z += e.z; s.w += e.w;
    }
    ((float4*)g_Psum)[seg * PIX4 + p4] = s;
}

// ---------------------------------------------------------------------------
// Kernel B2: exclusive prefix of g_Psum along segments (per scalar pixel).
// ---------------------------------------------------------------------------
__global__ __launch_bounds__(256) void prefix_kernel()
{
    const int p = blockIdx.x * 256 + threadIdx.x;     // < PIX
    float run = 0.f;
#pragma unroll 10
    for (int s = 0; s < NSEG; s++) {
        const float v = g_Psum[s * PIX + p];
        g_Ppre[s * PIX + p] = run;
        run += v;
    }
}

// ---------------------------------------------------------------------------
// Kernel C: offset (one load) + local scan + combine (float4, deep unroll).
// ---------------------------------------------------------------------------
__global__ __launch_bounds__(256) void scan_combine_kernel(
    float*       __restrict__ dst,          // (T+1, C, H, W)
    const float* __restrict__ xT,           // first image of original x
    const float* __restrict__ alpha_ratio,  // (T,)
    const float* __restrict__ epc)          // (T,)
{
    const int seg = blockIdx.y;
    const int p4  = blockIdx.x * 256 + threadIdx.x;   // < PIX4

    float4 acc = ((const float4*)g_Ppre)[seg * PIX4 + p4];

    const float4 xv = ((const float4*)xT)[p4];
    if (seg == 0)
        ((float4*)dst)[p4] = xv;             // image 0 stays xT

    const int t0 = seg * SEGLEN;
#pragma unroll 10
    for (int j = t0; j < t0 + SEGLEN; j++) {
        float4 e = __ldcs((const float4*)g_E + (size_t)j * PIX4 + p4);
        acc.x += e.x; acc.y += e.y; acc.z += e.z; acc.w += e.w;
        const float ar = __ldg(alpha_ratio + j);
        const float ep = __ldg(epc + j);
        float4 o;
        o.x = fmaf(ar, xv.x, ep * acc.x);
        o.y = fmaf(ar, xv.y, ep * acc.y);
        o.z = fmaf(ar, xv.z, ep * acc.z);
        o.w = fmaf(ar, xv.w, ep * acc.w);
        ((float4*)dst)[(size_t)(j + 1) * PIX4 + p4] = o;
    }
}

extern "C" void kernel_launch(void* const* d_in, const int* in_sizes, int n_in,
                              void* d_out, int out_size)
{
    const float* x           = (const float*)d_in[0];  // (T+1, 3, 64, 64)
    const int*   t_arr       = (const int*)  d_in[1];  // (T,)
    const float* alpha_ratio = (const float*)d_in[2];  // (T,1,1,1)
    const float* et_coeff    = (const float*)d_in[3];  // (T,1,1,1)
    const float* epc         = (const float*)d_in[4];  // (T,1,1,1)
    const float* conv_w      = (const float*)d_in[5];  // (3,3,3,3)
    const float* temb        = (const float*)d_in[6];  // (T, 3)
    float*       out         = (float*)d_out;

    cudaMemcpyToSymbolAsync(c_w, conv_w, 81 * sizeof(float), 0,
                            cudaMemcpyDeviceToDevice);

    dim3 gA(H_DIM / TILE_ROWS, T_STEPS), bA(256);      // (4, 1000)
    dim3 gB(PIX4 / 256, NSEG),           bB(256);      // (12, 50)
    dim3 gP(PIX / 256),                  bP(256);      // (48)
    dim3 gC(PIX4 / 256, NSEG),           bC(256);      // (12, 50)

    for (int it = 0; it < 3; it++) {
        const float* src = (it == 0) ? x : out;  // conv reads images 0..T-1
        conv_kernel<<<gA, bA>>>(src, temb, t_arr, et_coeff);
        psum_kernel<<<gB, bB>>>();
        prefix_kernel<<<gP, bP>>>();
        scan_combine_kernel<<<gC, bC>>>(out, x, alpha_ratio, epc);
    }
}